// round 1
// baseline (speedup 1.0000x reference)
#include <cuda_runtime.h>

#define NPX 16384
#define NQ  8
#define NB  5

// Scratch (no allocation allowed): conv output angles + precomputed gate matrices.
__device__ float  d_ang[NPX * NQ];
__device__ float2 d_gmats[(2 * NB * NQ) * 4];   // 80 2x2 complex mats: [0..39]=U3, [40..79]=CU3-inner-U3

// ---------------------------------------------------------------------------
// Kernel 0: precompute all gate matrices from u3/cu3 params (80 matrices).
// u3(th,ph,la) = [[c, -e^{i la} s], [e^{i ph} s, e^{i(ph+la)} c]], c=cos(th/2), s=sin(th/2)
// ---------------------------------------------------------------------------
__global__ void setup_gates(const float* __restrict__ u3p, const float* __restrict__ cu3p) {
    int t = threadIdx.x;
    if (t >= 80) return;
    const float* p = (t < 40) ? (u3p + 3 * t) : (cu3p + 3 * (t - 40));
    float th = p[0], ph = p[1], la = p[2];
    float s, c;     sincosf(0.5f * th, &s, &c);
    float sl, cl;   sincosf(la, &sl, &cl);
    float sp, cp;   sincosf(ph, &sp, &cp);
    float spl, cpl; sincosf(ph + la, &spl, &cpl);
    float2* g = &d_gmats[t * 4];
    g[0] = make_float2(c, 0.0f);
    g[1] = make_float2(-cl * s, -sl * s);
    g[2] = make_float2(cp * s, sp * s);
    g[3] = make_float2(cpl * c, spl * c);
}

// ---------------------------------------------------------------------------
// Kernel 1: 3x3 SAME conv, 16 -> 8 channels, writes per-pixel encoding angles.
// x: [4,16,64,64] NCHW, w: [8,16,3,3] OIHW. ang[p][q], p = ((b*64)+h)*64+w.
// ---------------------------------------------------------------------------
__global__ void conv_kernel(const float* __restrict__ x,
                            const float* __restrict__ cw,
                            const float* __restrict__ cb) {
    __shared__ float sw[NQ * 16 * 9];
    __shared__ float sb[NQ];
    int tid = threadIdx.x;
    for (int i = tid; i < NQ * 144; i += blockDim.x) sw[i] = cw[i];
    if (tid < NQ) sb[tid] = cb[tid];
    __syncthreads();

    int p = blockIdx.x * blockDim.x + tid;
    if (p >= NPX) return;
    int bN = p >> 12;
    int h  = (p >> 6) & 63;
    int wd = p & 63;

    float acc[NQ];
#pragma unroll
    for (int q = 0; q < NQ; q++) acc[q] = sb[q];

    for (int ci = 0; ci < 16; ci++) {
        const float* xp = x + ((bN * 16 + ci) << 12);
#pragma unroll
        for (int kh = 0; kh < 3; kh++) {
            int hh = h + kh - 1;
            if (hh < 0 || hh > 63) continue;
#pragma unroll
            for (int kw = 0; kw < 3; kw++) {
                int ww = wd + kw - 1;
                if (ww < 0 || ww > 63) continue;
                float xv = xp[hh * 64 + ww];
                int widx = ci * 9 + kh * 3 + kw;
#pragma unroll
                for (int q = 0; q < NQ; q++) acc[q] += xv * sw[q * 144 + widx];
            }
        }
    }
#pragma unroll
    for (int q = 0; q < NQ; q++) d_ang[p * NQ + q] = acc[q];
}

// ---------------------------------------------------------------------------
// Complex 2x2 gate on amplitude pair (i0, i1) in shared memory.
// ---------------------------------------------------------------------------
__device__ __forceinline__ void cgate(float* re, float* im, int i0, int i1,
                                      float2 u00, float2 u01, float2 u10, float2 u11) {
    float a0r = re[i0], a0i = im[i0], a1r = re[i1], a1i = im[i1];
    float n0r = u00.x * a0r - u00.y * a0i + u01.x * a1r - u01.y * a1i;
    float n0i = u00.x * a0i + u00.y * a0r + u01.x * a1i + u01.y * a1r;
    float n1r = u10.x * a0r - u10.y * a0i + u11.x * a1r - u11.y * a1i;
    float n1i = u10.x * a0i + u10.y * a0r + u11.x * a1i + u11.y * a1r;
    re[i0] = n0r; im[i0] = n0i;
    re[i1] = n1r; im[i1] = n1i;
}

// <Z_q> over all 8 wires (wire w <-> bit 7-w). Lane 0 writes mout[0..7].
__device__ __forceinline__ void measure_z(const float* re, const float* im,
                                          int lane, float* mout) {
    float part[NQ];
#pragma unroll
    for (int w = 0; w < NQ; w++) part[w] = 0.0f;
#pragma unroll
    for (int k = 0; k < 8; k++) {
        int i = lane + 32 * k;
        float pr = re[i], pi = im[i];
        float p = pr * pr + pi * pi;
#pragma unroll
        for (int w = 0; w < NQ; w++)
            part[w] += ((i >> (7 - w)) & 1) ? -p : p;
    }
#pragma unroll
    for (int w = 0; w < NQ; w++) {
#pragma unroll
        for (int o = 16; o; o >>= 1)
            part[w] += __shfl_xor_sync(0xffffffffu, part[w], o);
    }
    if (lane == 0) {
#pragma unroll
        for (int w = 0; w < NQ; w++) mout[w] = part[w];
    }
    __syncwarp();  // all state reads done before subsequent gate writes
}

// ---------------------------------------------------------------------------
// Kernel 2: one warp per pixel. State (256 complex) in shared memory.
// 4 warps / block, grid = NPX/4.
// ---------------------------------------------------------------------------
__global__ void __launch_bounds__(128)
sim_kernel(const float* __restrict__ fc_w, const float* __restrict__ fc_b,
           float* __restrict__ out) {
    __shared__ float  sre[4 * 256];
    __shared__ float  sim_[4 * 256];
    __shared__ float2 sg[320];
    __shared__ float  smeas[4][24];

    int t = threadIdx.x;
    int wp = t >> 5, lane = t & 31;
    int pix = blockIdx.x * 4 + wp;

    for (int i = t; i < 320; i += 128) sg[i] = d_gmats[i];

    float* re = sre  + wp * 256;
    float* im = sim_ + wp * 256;

    // RY encoding: product state, st[i] = prod_w (bit(i,7-w) ? sin : cos)(ang_w/2)
    float cv[NQ], sv[NQ];
#pragma unroll
    for (int w = 0; w < NQ; w++) {
        float a = d_ang[pix * NQ + w];
        sincosf(0.5f * a, &sv[w], &cv[w]);
    }
    __syncthreads();  // gate matrices ready

#pragma unroll
    for (int k = 0; k < 8; k++) {
        int i = lane + 32 * k;
        float v = 1.0f;
#pragma unroll
        for (int w = 0; w < NQ; w++) v *= ((i >> (7 - w)) & 1) ? sv[w] : cv[w];
        re[i] = v; im[i] = 0.0f;
    }
    __syncwarp();

    // 5 blocks of (8 U3 + 8 circular CU3)
    for (int b = 0; b < NB; b++) {
        for (int w = 0; w < NQ; w++) {
            const float2* g = &sg[(b * NQ + w) * 4];
            float2 u00 = g[0], u01 = g[1], u10 = g[2], u11 = g[3];
            int q = 7 - w, m = 1 << q;
#pragma unroll
            for (int k = 0; k < 4; k++) {
                int pi = lane + 32 * k;
                int i0 = ((pi & ~(m - 1)) << 1) | (pi & (m - 1));
                cgate(re, im, i0, i0 | m, u00, u01, u10, u11);
            }
            __syncwarp();
        }
        for (int w = 0; w < NQ; w++) {
            const float2* g = &sg[(40 + b * NQ + w) * 4];
            float2 u00 = g[0], u01 = g[1], u10 = g[2], u11 = g[3];
            int qc = 7 - w;
            int qt = 7 - ((w + 1) & 7);
            int cm = 1 << qc, tm = 1 << qt;
            int ql = qc < qt ? qc : qt, qh = qc < qt ? qt : qc;
            int ml = 1 << ql, mh = 1 << qh;
#pragma unroll
            for (int k = 0; k < 2; k++) {
                int pi = lane + 32 * k;
                int i = ((pi & ~(ml - 1)) << 1) | (pi & (ml - 1));
                i = ((i & ~(mh - 1)) << 1) | (i & (mh - 1));
                cgate(re, im, i | cm, i | cm | tm, u00, u01, u10, u11);
            }
            __syncwarp();
        }
    }

    // MeasureAll(Z)
    measure_z(re, im, lane, &smeas[wp][0]);

    // H on every wire (diagonalize X), then measure
    const float R = 0.70710678118654752f;
    {
        float2 h00 = make_float2(R, 0), h01 = make_float2(R, 0);
        float2 h10 = make_float2(R, 0), h11 = make_float2(-R, 0);
        for (int q = 0; q < NQ; q++) {
            int m = 1 << q;
#pragma unroll
            for (int k = 0; k < 4; k++) {
                int pi = lane + 32 * k;
                int i0 = ((pi & ~(m - 1)) << 1) | (pi & (m - 1));
                cgate(re, im, i0, i0 | m, h00, h01, h10, h11);
            }
            __syncwarp();
        }
    }
    measure_z(re, im, lane, &smeas[wp][8]);

    // YROT = H @ diag(1,-i) = r*[[1,-i],[1,i]] on every wire, then measure
    {
        float2 y00 = make_float2(R, 0), y01 = make_float2(0, -R);
        float2 y10 = make_float2(R, 0), y11 = make_float2(0, R);
        for (int q = 0; q < NQ; q++) {
            int m = 1 << q;
#pragma unroll
            for (int k = 0; k < 4; k++) {
                int pi = lane + 32 * k;
                int i0 = ((pi & ~(m - 1)) << 1) | (pi & (m - 1));
                cgate(re, im, i0, i0 | m, y00, y01, y10, y11);
            }
            __syncwarp();
        }
    }
    measure_z(re, im, lane, &smeas[wp][16]);
    __syncwarp();

    // Fused FC: out[c] = fc_b[c] + sum_j meas[j] * fc_w[c][j]; one lane per channel.
    float o = fc_b[lane];
#pragma unroll
    for (int j = 0; j < 24; j++) o += smeas[wp][j] * fc_w[lane * 24 + j];
    int bN = pix >> 12, hw = pix & 4095;
    out[(bN * 32 + lane) * 4096 + hw] = o;
}

// ---------------------------------------------------------------------------
extern "C" void kernel_launch(void* const* d_in, const int* in_sizes, int n_in,
                              void* d_out, int out_size) {
    const float* x      = (const float*)d_in[0];
    const float* conv_w = (const float*)d_in[1];
    const float* conv_b = (const float*)d_in[2];
    const float* u3p    = (const float*)d_in[3];
    const float* cu3p   = (const float*)d_in[4];
    const float* fc_w   = (const float*)d_in[5];
    const float* fc_b   = (const float*)d_in[6];
    float* out = (float*)d_out;

    setup_gates<<<1, 96>>>(u3p, cu3p);
    conv_kernel<<<NPX / 256, 256>>>(x, conv_w, conv_b);
    sim_kernel<<<NPX / 4, 128>>>(fc_w, fc_b, out);
}

// round 2
// speedup vs baseline: 3.4215x; 3.4215x over previous
#include <cuda_runtime.h>

#define NPX 16384
#define FULL 0xffffffffu

// Scratch (no allocation allowed): conv output angles + precomputed gate matrices.
__device__ float  d_ang[NPX * 8];
__device__ float2 d_gmats[320];   // 80 2x2 complex mats: [0..39]=U3, [40..79]=CU3-inner-U3

// ---------------------------------------------------------------------------
// Kernel 1: 3x3 SAME conv 16->8ch (64 threads/block => 256 blocks fill the chip)
// + last block computes the 80 gate matrices.
// ---------------------------------------------------------------------------
__global__ void __launch_bounds__(64)
conv_kernel(const float* __restrict__ x, const float* __restrict__ cw,
            const float* __restrict__ cb, const float* __restrict__ u3p,
            const float* __restrict__ cu3p) {
    if (blockIdx.x == gridDim.x - 1) {
        // gate setup: u3(th,ph,la) = [[c, -e^{i la} s],[e^{i ph} s, e^{i(ph+la)} c]]
        for (int t = threadIdx.x; t < 80; t += 64) {
            const float* p = (t < 40) ? (u3p + 3 * t) : (cu3p + 3 * (t - 40));
            float th = p[0], ph = p[1], la = p[2];
            float s, c;     sincosf(0.5f * th, &s, &c);
            float sl, cl;   sincosf(la, &sl, &cl);
            float sp, cp;   sincosf(ph, &sp, &cp);
            float spl, cpl; sincosf(ph + la, &spl, &cpl);
            float2* g = &d_gmats[t * 4];
            g[0] = make_float2(c, 0.0f);
            g[1] = make_float2(-cl * s, -sl * s);
            g[2] = make_float2(cp * s, sp * s);
            g[3] = make_float2(cpl * c, spl * c);
        }
        return;
    }
    __shared__ float swt[8 * 144];
    __shared__ float sb[8];
    int tid = threadIdx.x;
    for (int i = tid; i < 8 * 144; i += 64) swt[i] = cw[i];
    if (tid < 8) sb[tid] = cb[tid];
    __syncthreads();

    int p  = blockIdx.x * 64 + tid;
    int bN = p >> 12, h = (p >> 6) & 63, wd = p & 63;

    float acc[8];
#pragma unroll
    for (int q = 0; q < 8; q++) acc[q] = sb[q];

    for (int ci = 0; ci < 16; ci++) {
        const float* xp = x + ((bN * 16 + ci) << 12);
#pragma unroll
        for (int kh = 0; kh < 3; kh++) {
            int hh = h + kh - 1;
            if (hh < 0 || hh > 63) continue;
#pragma unroll
            for (int kw = 0; kw < 3; kw++) {
                int ww = wd + kw - 1;
                if (ww < 0 || ww > 63) continue;
                float xv = xp[hh * 64 + ww];
                int widx = ci * 9 + kh * 3 + kw;
#pragma unroll
                for (int q = 0; q < 8; q++) acc[q] += xv * swt[q * 144 + widx];
            }
        }
    }
#pragma unroll
    for (int q = 0; q < 8; q++) d_ang[p * 8 + q] = acc[q];
}

// ---------------------------------------------------------------------------
// Register-resident gate primitives. Amplitude index i = lane + 32*k:
// bits 0..4 = lane bits, bits 5..7 = k bits 0..2. Wire w <-> bit q = 7-w.
// ---------------------------------------------------------------------------
__device__ __forceinline__ void cpair(float& a0r, float& a0i, float& a1r, float& a1i,
                                      float2 u00, float2 u01, float2 u10, float2 u11) {
    float n0r = u00.x * a0r - u00.y * a0i + u01.x * a1r - u01.y * a1i;
    float n0i = u00.x * a0i + u00.y * a0r + u01.x * a1i + u01.y * a1r;
    float n1r = u10.x * a0r - u10.y * a0i + u11.x * a1r - u11.y * a1i;
    float n1i = u10.x * a0i + u10.y * a0r + u11.x * a1i + u11.y * a1r;
    a0r = n0r; a0i = n0i; a1r = n1r; a1i = n1i;
}

// Gate on k-bit KB (in-register). CMASK/CVAL restrict to controlled subspace.
template <int KB, int CMASK, int CVAL>
__device__ __forceinline__ void gate_reg(float* ar, float* ai,
                                         float2 u00, float2 u01, float2 u10, float2 u11) {
#pragma unroll
    for (int k0 = 0; k0 < 8; k0++)
        if (!(k0 & (1 << KB)) && ((k0 & CMASK) == CVAL)) {
            int k1 = k0 | (1 << KB);
            cpair(ar[k0], ai[k0], ar[k1], ai[k1], u00, u01, u10, u11);
        }
}

// Gate on lane-bit Q via shfl_xor. Coeffs d0 (my amp) / d1 (partner) preselected.
template <int Q, int KMASK>
__device__ __forceinline__ void gate_lane_core(float* ar, float* ai, float2 d0, float2 d1) {
#pragma unroll
    for (int k = 0; k < 8; k++) {
        if ((k & KMASK) != KMASK) continue;   // reg-control restriction (KMASK=0 => all)
        float orr = __shfl_xor_sync(FULL, ar[k], 1 << Q);
        float oii = __shfl_xor_sync(FULL, ai[k], 1 << Q);
        float nr = d0.x * ar[k] - d0.y * ai[k] + d1.x * orr - d1.y * oii;
        float ni = d0.x * ai[k] + d0.y * ar[k] + d1.x * oii + d1.y * orr;
        ar[k] = nr; ai[k] = ni;
    }
}

template <int Q>
__device__ __forceinline__ void gate_lane(float* ar, float* ai, int lane,
                                          float2 u00, float2 u01, float2 u10, float2 u11) {
    int b = (lane >> Q) & 1;
    float2 d0 = b ? u11 : u00;
    float2 d1 = b ? u10 : u01;
    gate_lane_core<Q, 0>(ar, ai, d0, d1);
}

// lane-target, reg-control (control k-bit CB must be 1)
template <int Q, int CB>
__device__ __forceinline__ void gate_lane_kctrl(float* ar, float* ai, int lane,
                                                float2 u00, float2 u01, float2 u10, float2 u11) {
    int b = (lane >> Q) & 1;
    float2 d0 = b ? u11 : u00;
    float2 d1 = b ? u10 : u01;
    gate_lane_core<Q, (1 << CB)>(ar, ai, d0, d1);
}

// lane-target, lane-control (control lane-bit CQ): identity for ctrl=0 lanes
template <int Q, int CQ>
__device__ __forceinline__ void gate_lane_lctrl(float* ar, float* ai, int lane,
                                                float2 u00, float2 u01, float2 u10, float2 u11) {
    int b = (lane >> Q) & 1;
    int ctrl = (lane >> CQ) & 1;
    float2 d0 = ctrl ? (b ? u11 : u00) : make_float2(1.0f, 0.0f);
    float2 d1 = ctrl ? (b ? u10 : u01) : make_float2(0.0f, 0.0f);
    gate_lane_core<Q, 0>(ar, ai, d0, d1);
}

// reg-target (k-bit KB), lane-control (lane bit CQ): identity for ctrl=0 lanes
template <int KB, int CQ>
__device__ __forceinline__ void gate_reg_lctrl(float* ar, float* ai, int lane,
                                               float2 u00, float2 u01, float2 u10, float2 u11) {
    int ctrl = (lane >> CQ) & 1;
    float2 v00 = ctrl ? u00 : make_float2(1.0f, 0.0f);
    float2 v01 = ctrl ? u01 : make_float2(0.0f, 0.0f);
    float2 v10 = ctrl ? u10 : make_float2(0.0f, 0.0f);
    float2 v11 = ctrl ? u11 : make_float2(1.0f, 0.0f);
    gate_reg<KB, 0, 0>(ar, ai, v00, v01, v10, v11);
}

// <Z_w> for all 8 wires; every lane ends with identical m[0..7].
__device__ __forceinline__ void measure(const float* ar, const float* ai, int lane, float* m) {
    float p[8];
#pragma unroll
    for (int k = 0; k < 8; k++) p[k] = ar[k] * ar[k] + ai[k] * ai[k];
    float a = p[0] + p[1], b = p[2] + p[3], c = p[4] + p[5], d = p[6] + p[7];
    float e = p[0] + p[2], f = p[4] + p[6], g = p[1] + p[3], h = p[5] + p[7];
    float t  = (a + b) + (c + d);
    float m0 = (a + b) - (c + d);   // wire0: k-bit2
    float m1 = (a + c) - (b + d);   // wire1: k-bit1
    float m2 = (e + f) - (g + h);   // wire2: k-bit0
#pragma unroll
    for (int o = 16; o; o >>= 1) {
        m0 += __shfl_xor_sync(FULL, m0, o);
        m1 += __shfl_xor_sync(FULL, m1, o);
        m2 += __shfl_xor_sync(FULL, m2, o);
    }
    m[0] = m0; m[1] = m1; m[2] = m2;
#pragma unroll
    for (int w = 3; w < 8; w++) {
        int q = 7 - w;                        // lane bit
        float v = ((lane >> q) & 1) ? -t : t;
#pragma unroll
        for (int o = 16; o; o >>= 1) v += __shfl_xor_sync(FULL, v, o);
        m[w] = v;
    }
}

// ---------------------------------------------------------------------------
// Kernel 2: one warp per pixel, statevector entirely in registers.
// ---------------------------------------------------------------------------
__global__ void __launch_bounds__(128)
sim_kernel(const float* __restrict__ fc_w, const float* __restrict__ fc_b,
           float* __restrict__ out) {
    __shared__ float2 sg[320];
    int t = threadIdx.x, wp = t >> 5, lane = t & 31;
    int pix = blockIdx.x * 4 + wp;

    for (int i = t; i < 320; i += 128) sg[i] = d_gmats[i];

    // RY encoding angles: lanes 0..7 each compute one sincos, broadcast.
    float mys = 0.0f, myc = 1.0f;
    if (lane < 8) {
        float a = d_ang[pix * 8 + lane];
        sincosf(0.5f * a, &mys, &myc);
    }
    float cw[8], sw_[8];
#pragma unroll
    for (int w = 0; w < 8; w++) {
        cw[w]  = __shfl_sync(FULL, myc, w);
        sw_[w] = __shfl_sync(FULL, mys, w);
    }
    // product state: amp(i) = prod_w (bit_{7-w}(i) ? s_w : c_w)
    float lf = 1.0f;
#pragma unroll
    for (int q = 0; q < 5; q++) {               // lane bits 0..4 = wires 7..3
        int w = 7 - q;
        lf *= ((lane >> q) & 1) ? sw_[w] : cw[w];
    }
    float ar[8], ai[8];
#pragma unroll
    for (int k = 0; k < 8; k++) {
        float v = lf;
        v *= (k & 1) ? sw_[2] : cw[2];          // k-bit0 = wire 2
        v *= (k & 2) ? sw_[1] : cw[1];
        v *= (k & 4) ? sw_[0] : cw[0];
        ar[k] = v; ai[k] = 0.0f;
    }
    __syncthreads();   // sg ready

#define G4(base) sg[(base)*4], sg[(base)*4+1], sg[(base)*4+2], sg[(base)*4+3]

    // 5 blocks: 8 U3 then circular CU3 ring
    for (int b = 0; b < 5; b++) {
        int u = b * 8;
        gate_reg<2, 0, 0>(ar, ai, G4(u + 0));            // wire0 -> k-bit2
        gate_reg<1, 0, 0>(ar, ai, G4(u + 1));            // wire1 -> k-bit1
        gate_reg<0, 0, 0>(ar, ai, G4(u + 2));            // wire2 -> k-bit0
        gate_lane<4>(ar, ai, lane, G4(u + 3));           // wire3 -> lane bit4
        gate_lane<3>(ar, ai, lane, G4(u + 4));
        gate_lane<2>(ar, ai, lane, G4(u + 5));
        gate_lane<1>(ar, ai, lane, G4(u + 6));
        gate_lane<0>(ar, ai, lane, G4(u + 7));           // wire7 -> lane bit0

        int cu = 40 + b * 8;
        gate_reg<1, 4, 4>(ar, ai, G4(cu + 0));           // c=w0(kb2), t=w1(kb1)
        gate_reg<0, 2, 2>(ar, ai, G4(cu + 1));           // c=w1(kb1), t=w2(kb0)
        gate_lane_kctrl<4, 0>(ar, ai, lane, G4(cu + 2)); // c=w2(kb0), t=w3(lane4)
        gate_lane_lctrl<3, 4>(ar, ai, lane, G4(cu + 3)); // c=w3, t=w4
        gate_lane_lctrl<2, 3>(ar, ai, lane, G4(cu + 4));
        gate_lane_lctrl<1, 2>(ar, ai, lane, G4(cu + 5));
        gate_lane_lctrl<0, 1>(ar, ai, lane, G4(cu + 6));
        gate_reg_lctrl<2, 0>(ar, ai, lane, G4(cu + 7));  // c=w7(lane0), t=w0(kb2)
    }

    float meas[24];
    measure(ar, ai, lane, meas);                          // Z

    const float R = 0.70710678118654752f;
    {   // H on every wire, then measure (X basis)
        float2 h00 = make_float2(R, 0), h01 = make_float2(R, 0);
        float2 h10 = make_float2(R, 0), h11 = make_float2(-R, 0);
        gate_reg<2, 0, 0>(ar, ai, h00, h01, h10, h11);
        gate_reg<1, 0, 0>(ar, ai, h00, h01, h10, h11);
        gate_reg<0, 0, 0>(ar, ai, h00, h01, h10, h11);
        gate_lane<4>(ar, ai, lane, h00, h01, h10, h11);
        gate_lane<3>(ar, ai, lane, h00, h01, h10, h11);
        gate_lane<2>(ar, ai, lane, h00, h01, h10, h11);
        gate_lane<1>(ar, ai, lane, h00, h01, h10, h11);
        gate_lane<0>(ar, ai, lane, h00, h01, h10, h11);
    }
    measure(ar, ai, lane, meas + 8);
    {   // YROT = H @ diag(1,-i) = R*[[1,-i],[1,i]], then measure (Y basis)
        float2 y00 = make_float2(R, 0), y01 = make_float2(0, -R);
        float2 y10 = make_float2(R, 0), y11 = make_float2(0, R);
        gate_reg<2, 0, 0>(ar, ai, y00, y01, y10, y11);
        gate_reg<1, 0, 0>(ar, ai, y00, y01, y10, y11);
        gate_reg<0, 0, 0>(ar, ai, y00, y01, y10, y11);
        gate_lane<4>(ar, ai, lane, y00, y01, y10, y11);
        gate_lane<3>(ar, ai, lane, y00, y01, y10, y11);
        gate_lane<2>(ar, ai, lane, y00, y01, y10, y11);
        gate_lane<1>(ar, ai, lane, y00, y01, y10, y11);
        gate_lane<0>(ar, ai, lane, y00, y01, y10, y11);
    }
    measure(ar, ai, lane, meas + 16);

    // Fused FC: one lane per output channel (meas[] is warp-uniform).
    float o = __ldg(&fc_b[lane]);
#pragma unroll
    for (int j = 0; j < 24; j++) o += meas[j] * __ldg(&fc_w[lane * 24 + j]);
    int bN = pix >> 12, hw = pix & 4095;
    out[(bN * 32 + lane) * 4096 + hw] = o;
#undef G4
}

// ---------------------------------------------------------------------------
extern "C" void kernel_launch(void* const* d_in, const int* in_sizes, int n_in,
                              void* d_out, int out_size) {
    const float* x      = (const float*)d_in[0];
    const float* conv_w = (const float*)d_in[1];
    const float* conv_b = (const float*)d_in[2];
    const float* u3p    = (const float*)d_in[3];
    const float* cu3p   = (const float*)d_in[4];
    const float* fc_w   = (const float*)d_in[5];
    const float* fc_b   = (const float*)d_in[6];
    float* out = (float*)d_out;

    conv_kernel<<<NPX / 64 + 1, 64>>>(x, conv_w, conv_b, u3p, cu3p);
    sim_kernel<<<NPX / 4, 128>>>(fc_w, fc_b, out);
}

// round 3
// speedup vs baseline: 5.0887x; 1.4873x over previous
#include <cuda_runtime.h>

#define NPX 16384
#define FULL 0xffffffffu

// Scratch: conv output angles + fused gate matrices.
// d_fg4[t*4 .. t*4+3] for t = b*8+w (40 fused CU3 gates):
//   [0] = A row0 (A00, A01)   [1] = A row1 swizzled (A11, A10)
//   [2] = B row0 (B00, B01)   [3] = B row1 swizzled (B11, B10)
// A = ctrl-0 matrix, B = ctrl-1 matrix (U3 fused in).
// d_fg4[160..161] = U3(block0, wire0) in normal row order (for init fold).
__device__ float  d_ang[NPX * 8];
__device__ float4 d_fg4[162];

// ---------------------------------------------------------------------------
// complex 2x2 helpers (setup only)
// ---------------------------------------------------------------------------
__device__ __forceinline__ float2 cmul(float2 a, float2 b) {
    return make_float2(a.x * b.x - a.y * b.y, a.x * b.y + a.y * b.x);
}
__device__ __forceinline__ float2 cadd(float2 a, float2 b) {
    return make_float2(a.x + b.x, a.y + b.y);
}
__device__ void u3m(const float* p, float2* M) {
    float th = p[0], ph = p[1], la = p[2];
    float s, c;     sincosf(0.5f * th, &s, &c);
    float sl, cl;   sincosf(la, &sl, &cl);
    float sp, cp;   sincosf(ph, &sp, &cp);
    float spl, cpl; sincosf(ph + la, &spl, &cpl);
    M[0] = make_float2(c, 0.0f);
    M[1] = make_float2(-cl * s, -sl * s);
    M[2] = make_float2(cp * s, sp * s);
    M[3] = make_float2(cpl * c, spl * c);
}
__device__ void mm2(const float2* X, const float2* Y, float2* Z) {  // Z = X @ Y
    Z[0] = cadd(cmul(X[0], Y[0]), cmul(X[1], Y[2]));
    Z[1] = cadd(cmul(X[0], Y[1]), cmul(X[1], Y[3]));
    Z[2] = cadd(cmul(X[2], Y[0]), cmul(X[3], Y[2]));
    Z[3] = cadd(cmul(X[2], Y[1]), cmul(X[3], Y[3]));
}

// ---------------------------------------------------------------------------
// Kernel 1: 3x3 SAME conv 16->8ch + last block computes fused gate matrices.
// ---------------------------------------------------------------------------
__global__ void __launch_bounds__(64)
conv_kernel(const float* __restrict__ x, const float* __restrict__ cw,
            const float* __restrict__ cb, const float* __restrict__ u3p,
            const float* __restrict__ cu3p) {
    if (blockIdx.x == gridDim.x - 1) {
        int t = threadIdx.x;
        if (t == 40) {   // U3(0,0) for init fold, normal rows
            float2 M[4];
            u3m(u3p, M);
            d_fg4[160] = make_float4(M[0].x, M[0].y, M[1].x, M[1].y);
            d_fg4[161] = make_float4(M[2].x, M[2].y, M[3].x, M[3].y);
        }
        if (t < 40) {
            int b = t >> 3, w = t & 7;
            float2 U[4], C[4], B[4];
            if (w < 7)      u3m(u3p + (b * 8 + w + 1) * 3, U);
            else if (b < 4) u3m(u3p + ((b + 1) * 8) * 3, U);
            else { U[0] = make_float2(1, 0); U[1] = make_float2(0, 0);
                   U[2] = make_float2(0, 0); U[3] = make_float2(1, 0); }
            u3m(cu3p + (b * 8 + w) * 3, C);
            if (w < 7) mm2(C, U, B);   // U3 first, then CU3
            else       mm2(U, C, B);   // CU3(7,0) first, then next-block U3(.,0)
            float4* o = d_fg4 + t * 4;
            o[0] = make_float4(U[0].x, U[0].y, U[1].x, U[1].y);
            o[1] = make_float4(U[3].x, U[3].y, U[2].x, U[2].y);
            o[2] = make_float4(B[0].x, B[0].y, B[1].x, B[1].y);
            o[3] = make_float4(B[3].x, B[3].y, B[2].x, B[2].y);
        }
        return;
    }
    __shared__ float swt[8 * 144];
    __shared__ float sb[8];
    int tid = threadIdx.x;
    for (int i = tid; i < 8 * 144; i += 64) swt[i] = cw[i];
    if (tid < 8) sb[tid] = cb[tid];
    __syncthreads();

    int p  = blockIdx.x * 64 + tid;
    int bN = p >> 12, h = (p >> 6) & 63, wd = p & 63;

    float acc[8];
#pragma unroll
    for (int q = 0; q < 8; q++) acc[q] = sb[q];

    for (int ci = 0; ci < 16; ci++) {
        const float* xp = x + ((bN * 16 + ci) << 12);
#pragma unroll
        for (int kh = 0; kh < 3; kh++) {
            int hh = h + kh - 1;
            if (hh < 0 || hh > 63) continue;
#pragma unroll
            for (int kw = 0; kw < 3; kw++) {
                int ww = wd + kw - 1;
                if (ww < 0 || ww > 63) continue;
                float xv = xp[hh * 64 + ww];
                int widx = ci * 9 + kh * 3 + kw;
#pragma unroll
                for (int q = 0; q < 8; q++) acc[q] += xv * swt[q * 144 + widx];
            }
        }
    }
#pragma unroll
    for (int q = 0; q < 8; q++) d_ang[p * 8 + q] = acc[q];
}

// ---------------------------------------------------------------------------
// Register-resident state: index i = lane + 32*k. Lane bits 0..4 = wires 7..3,
// k bits 0,1,2 = wires 2,1,0.
// ---------------------------------------------------------------------------
__device__ __forceinline__ void cpair(float& a0r, float& a0i, float& a1r, float& a1i,
                                      float2 u00, float2 u01, float2 u10, float2 u11) {
    float n0r = u00.x * a0r - u00.y * a0i + u01.x * a1r - u01.y * a1i;
    float n0i = u00.x * a0i + u00.y * a0r + u01.x * a1i + u01.y * a1r;
    float n1r = u10.x * a0r - u10.y * a0i + u11.x * a1r - u11.y * a1i;
    float n1i = u10.x * a0i + u10.y * a0r + u11.x * a1i + u11.y * a1r;
    a0r = n0r; a0i = n0i; a1r = n1r; a1i = n1i;
}

// lane-gate inner body: n = d0*mine + d1*partner(shfl_xor 1<<Q)
template <int Q>
__device__ __forceinline__ void lane_body(float* ar, float* ai, int k, float2 d0, float2 d1) {
    float orr = __shfl_xor_sync(FULL, ar[k], 1 << Q);
    float oii = __shfl_xor_sync(FULL, ai[k], 1 << Q);
    float nr = d0.x * ar[k] - d0.y * ai[k] + d1.x * orr - d1.y * oii;
    float ni = d0.x * ai[k] + d0.y * ar[k] + d1.x * oii + d1.y * orr;
    ar[k] = nr; ai[k] = ni;
}

// ---- fused CU3 gates (A = ctrl0, B = ctrl1, swizzled rows in g[0..3]) ----

// reg-ctrl (k-bit CB), reg-target (k-bit TB)
template <int TB, int CB>
__device__ __forceinline__ void fgate_rr(float* ar, float* ai, const float4* g) {
    float4 a0 = g[0], a1 = g[1], b0 = g[2], b1 = g[3];
#pragma unroll
    for (int k0 = 0; k0 < 8; k0++)
        if (!(k0 & (1 << TB))) {
            float4 r0 = (k0 & (1 << CB)) ? b0 : a0;
            float4 r1 = (k0 & (1 << CB)) ? b1 : a1;
            int k1 = k0 | (1 << TB);
            cpair(ar[k0], ai[k0], ar[k1], ai[k1],
                  make_float2(r0.x, r0.y), make_float2(r0.z, r0.w),
                  make_float2(r1.z, r1.w), make_float2(r1.x, r1.y));
        }
}

// reg-ctrl (k-bit 0), lane-target (lane bit 4): w=2 gate
__device__ __forceinline__ void fgate_lk(float* ar, float* ai, int lane, const float4* g) {
    int tb = (lane >> 4) & 1;
    float4 rA = g[tb];        // A row tb (diag-first)
    float4 rB = g[2 + tb];    // B row tb
    float2 d0A = make_float2(rA.x, rA.y), d1A = make_float2(rA.z, rA.w);
    float2 d0B = make_float2(rB.x, rB.y), d1B = make_float2(rB.z, rB.w);
#pragma unroll
    for (int k = 0; k < 8; k++)
        lane_body<4>(ar, ai, k, (k & 1) ? d0B : d0A, (k & 1) ? d1B : d1A);
}

// lane-ctrl (lane bit CQ), lane-target (lane bit Q)
template <int Q, int CQ>
__device__ __forceinline__ void fgate_ll(float* ar, float* ai, int lane, const float4* g) {
    int idx = (((lane >> CQ) & 1) << 1) | ((lane >> Q) & 1);
    float4 r = g[idx];        // one LDS.128: (d0, d1) ready
    float2 d0 = make_float2(r.x, r.y), d1 = make_float2(r.z, r.w);
#pragma unroll
    for (int k = 0; k < 8; k++) lane_body<Q>(ar, ai, k, d0, d1);
}

// lane-ctrl (lane bit 0), reg-target (k-bit 2): w=7 gate
__device__ __forceinline__ void fgate_rl(float* ar, float* ai, int lane, const float4* g) {
    const float4* M = g + ((lane & 1) << 1);
    float4 r0 = M[0], r1 = M[1];
    float2 u00 = make_float2(r0.x, r0.y), u01 = make_float2(r0.z, r0.w);
    float2 u11 = make_float2(r1.x, r1.y), u10 = make_float2(r1.z, r1.w);
#pragma unroll
    for (int k0 = 0; k0 < 4; k0++)
        cpair(ar[k0], ai[k0], ar[k0 + 4], ai[k0 + 4], u00, u01, u10, u11);
}

// ---- plain (uniform-matrix) gates for measurement basis changes ----
template <int KB>
__device__ __forceinline__ void gate_reg(float* ar, float* ai,
                                         float2 u00, float2 u01, float2 u10, float2 u11) {
#pragma unroll
    for (int k0 = 0; k0 < 8; k0++)
        if (!(k0 & (1 << KB))) {
            int k1 = k0 | (1 << KB);
            cpair(ar[k0], ai[k0], ar[k1], ai[k1], u00, u01, u10, u11);
        }
}
template <int Q>
__device__ __forceinline__ void gate_lane(float* ar, float* ai, int lane,
                                          float2 u00, float2 u01, float2 u10, float2 u11) {
    int b = (lane >> Q) & 1;
    float2 d0 = b ? u11 : u00;
    float2 d1 = b ? u10 : u01;
#pragma unroll
    for (int k = 0; k < 8; k++) lane_body<Q>(ar, ai, k, d0, d1);
}

// <Z_w> for all 8 wires; every lane ends with identical m[0..7].
__device__ __forceinline__ void measure(const float* ar, const float* ai, int lane, float* m) {
    float p[8];
#pragma unroll
    for (int k = 0; k < 8; k++) p[k] = ar[k] * ar[k] + ai[k] * ai[k];
    float a = p[0] + p[1], b = p[2] + p[3], c = p[4] + p[5], d = p[6] + p[7];
    float e = p[0] + p[2], f = p[4] + p[6], g = p[1] + p[3], h = p[5] + p[7];
    float t  = (a + b) + (c + d);
    float m0 = (a + b) - (c + d);
    float m1 = (a + c) - (b + d);
    float m2 = (e + f) - (g + h);
#pragma unroll
    for (int o = 16; o; o >>= 1) {
        m0 += __shfl_xor_sync(FULL, m0, o);
        m1 += __shfl_xor_sync(FULL, m1, o);
        m2 += __shfl_xor_sync(FULL, m2, o);
    }
    m[0] = m0; m[1] = m1; m[2] = m2;
#pragma unroll
    for (int w = 3; w < 8; w++) {
        int q = 7 - w;
        float v = ((lane >> q) & 1) ? -t : t;
#pragma unroll
        for (int o = 16; o; o >>= 1) v += __shfl_xor_sync(FULL, v, o);
        m[w] = v;
    }
}

// ---------------------------------------------------------------------------
// Kernel 2: one warp per pixel, statevector in registers, fused gates.
// ---------------------------------------------------------------------------
__global__ void __launch_bounds__(128)
sim_kernel(const float* __restrict__ fc_w, const float* __restrict__ fc_b,
           float* __restrict__ out) {
    __shared__ float4 sg[162];
    int t = threadIdx.x, wp = t >> 5, lane = t & 31;
    int pix = blockIdx.x * 4 + wp;

    for (int i = t; i < 162; i += 128) sg[i] = d_fg4[i];

    // RY encoding angles: lanes 0..7 compute sincos, broadcast.
    float mys = 0.0f, myc = 1.0f;
    if (lane < 8) {
        float a = d_ang[pix * 8 + lane];
        sincosf(0.5f * a, &mys, &myc);
    }
    float cw[8], sw_[8];
#pragma unroll
    for (int w = 0; w < 8; w++) {
        cw[w]  = __shfl_sync(FULL, myc, w);
        sw_[w] = __shfl_sync(FULL, mys, w);
    }
    float lf = 1.0f;
#pragma unroll
    for (int q = 0; q < 5; q++) {          // lane bits 0..4 = wires 7..3
        int w = 7 - q;
        lf *= ((lane >> q) & 1) ? sw_[w] : cw[w];
    }
    __syncthreads();   // sg ready

    // fold U3(block0, wire0) into the wire-0 initial vector
    float4 M0 = sg[160], M1 = sg[161];     // rows (M00,M01), (M10,M11)
    float v0r = M0.x * cw[0] + M0.z * sw_[0];
    float v0i = M0.y * cw[0] + M0.w * sw_[0];
    float v1r = M1.x * cw[0] + M1.z * sw_[0];
    float v1i = M1.y * cw[0] + M1.w * sw_[0];

    float ar[8], ai[8];
#pragma unroll
    for (int k = 0; k < 8; k++) {
        float rp = lf * ((k & 1) ? sw_[2] : cw[2]) * ((k & 2) ? sw_[1] : cw[1]);
        ar[k] = rp * ((k & 4) ? v1r : v0r);
        ai[k] = rp * ((k & 4) ? v1i : v0i);
    }

    // 5 blocks of 8 fused CU3 gates (U3 layers absorbed)
#pragma unroll 1
    for (int b = 0; b < 5; b++) {
        const float4* gb = sg + b * 32;
        fgate_rr<1, 2>(ar, ai, gb + 0);     // w=0: c=wire0(kb2), t=wire1(kb1)
        fgate_rr<0, 1>(ar, ai, gb + 4);     // w=1: c=kb1, t=kb0
        fgate_lk(ar, ai, lane, gb + 8);     // w=2: c=kb0, t=lane4
        fgate_ll<3, 4>(ar, ai, lane, gb + 12);  // w=3
        fgate_ll<2, 3>(ar, ai, lane, gb + 16);  // w=4
        fgate_ll<1, 2>(ar, ai, lane, gb + 20);  // w=5
        fgate_ll<0, 1>(ar, ai, lane, gb + 24);  // w=6
        fgate_rl(ar, ai, lane, gb + 28);    // w=7: c=lane0, t=kb2 (+next U3(.,0))
    }

    float meas[24];
    measure(ar, ai, lane, meas);                          // Z

    const float R = 0.70710678118654752f;
    {   // H on every wire -> X basis
        float2 h00 = make_float2(R, 0), h01 = make_float2(R, 0);
        float2 h10 = make_float2(R, 0), h11 = make_float2(-R, 0);
        gate_reg<2>(ar, ai, h00, h01, h10, h11);
        gate_reg<1>(ar, ai, h00, h01, h10, h11);
        gate_reg<0>(ar, ai, h00, h01, h10, h11);
        gate_lane<4>(ar, ai, lane, h00, h01, h10, h11);
        gate_lane<3>(ar, ai, lane, h00, h01, h10, h11);
        gate_lane<2>(ar, ai, lane, h00, h01, h10, h11);
        gate_lane<1>(ar, ai, lane, h00, h01, h10, h11);
        gate_lane<0>(ar, ai, lane, h00, h01, h10, h11);
    }
    measure(ar, ai, lane, meas + 8);
    {   // YROT = R*[[1,-i],[1,i]] -> Y basis
        float2 y00 = make_float2(R, 0), y01 = make_float2(0, -R);
        float2 y10 = make_float2(R, 0), y11 = make_float2(0, R);
        gate_reg<2>(ar, ai, y00, y01, y10, y11);
        gate_reg<1>(ar, ai, y00, y01, y10, y11);
        gate_reg<0>(ar, ai, y00, y01, y10, y11);
        gate_lane<4>(ar, ai, lane, y00, y01, y10, y11);
        gate_lane<3>(ar, ai, lane, y00, y01, y10, y11);
        gate_lane<2>(ar, ai, lane, y00, y01, y10, y11);
        gate_lane<1>(ar, ai, lane, y00, y01, y10, y11);
        gate_lane<0>(ar, ai, lane, y00, y01, y10, y11);
    }
    measure(ar, ai, lane, meas + 16);

    // Fused FC: one lane per output channel (meas[] is warp-uniform).
    float o = __ldg(&fc_b[lane]);
#pragma unroll
    for (int j = 0; j < 24; j++) o += meas[j] * __ldg(&fc_w[lane * 24 + j]);
    int bN = pix >> 12, hw = pix & 4095;
    out[(bN * 32 + lane) * 4096 + hw] = o;
}

// ---------------------------------------------------------------------------
extern "C" void kernel_launch(void* const* d_in, const int* in_sizes, int n_in,
                              void* d_out, int out_size) {
    const float* x      = (const float*)d_in[0];
    const float* conv_w = (const float*)d_in[1];
    const float* conv_b = (const float*)d_in[2];
    const float* u3p    = (const float*)d_in[3];
    const float* cu3p   = (const float*)d_in[4];
    const float* fc_w   = (const float*)d_in[5];
    const float* fc_b   = (const float*)d_in[6];
    float* out = (float*)d_out;

    conv_kernel<<<NPX / 64 + 1, 64>>>(x, conv_w, conv_b, u3p, cu3p);
    sim_kernel<<<NPX / 4, 128>>>(fc_w, fc_b, out);
}

// round 5
// speedup vs baseline: 6.4337x; 1.2643x over previous
#include <cuda_runtime.h>

#define NPX 16384
#define FULL 0xffffffffu

// Scratch: conv output angles + fused gate matrices.
// d_fg4[t*4 .. t*4+3] for t = b*8+w (40 fused CU3 gates):
//   [0] = A row0 (A00, A01)   [1] = A row1 swizzled (A11, A10)
//   [2] = B row0 (B00, B01)   [3] = B row1 swizzled (B11, B10)
// A = ctrl-0 matrix, B = ctrl-1 matrix (next U3 layer fused in).
// d_fg4[160..161] = U3(block0, wire0) normal rows (folded into init state).
__device__ float  d_ang[NPX * 8];
__device__ float4 d_fg4[162];

// ---------------------------------------------------------------------------
__device__ __forceinline__ float2 cmul(float2 a, float2 b) {
    return make_float2(a.x * b.x - a.y * b.y, a.x * b.y + a.y * b.x);
}
__device__ __forceinline__ float2 cadd(float2 a, float2 b) {
    return make_float2(a.x + b.x, a.y + b.y);
}
__device__ void u3m(const float* p, float2* M) {
    float th = p[0], ph = p[1], la = p[2];
    float s, c;     sincosf(0.5f * th, &s, &c);
    float sl, cl;   sincosf(la, &sl, &cl);
    float sp, cp;   sincosf(ph, &sp, &cp);
    float spl, cpl; sincosf(ph + la, &spl, &cpl);
    M[0] = make_float2(c, 0.0f);
    M[1] = make_float2(-cl * s, -sl * s);
    M[2] = make_float2(cp * s, sp * s);
    M[3] = make_float2(cpl * c, spl * c);
}
__device__ void mm2(const float2* X, const float2* Y, float2* Z) {  // Z = X @ Y
    Z[0] = cadd(cmul(X[0], Y[0]), cmul(X[1], Y[2]));
    Z[1] = cadd(cmul(X[0], Y[1]), cmul(X[1], Y[3]));
    Z[2] = cadd(cmul(X[2], Y[0]), cmul(X[3], Y[2]));
    Z[3] = cadd(cmul(X[2], Y[1]), cmul(X[3], Y[3]));
}

// ---------------------------------------------------------------------------
// Kernel 1: 3x3 SAME conv 16->8ch, 4 threads per pixel (ci split 4 ways).
// Last block computes the fused gate matrices.
// ---------------------------------------------------------------------------
__global__ void __launch_bounds__(128)
conv_kernel(const float* __restrict__ x, const float* __restrict__ cw,
            const float* __restrict__ cb, const float* __restrict__ u3p,
            const float* __restrict__ cu3p) {
    if (blockIdx.x == gridDim.x - 1) {
        int t = threadIdx.x;
        if (t == 40) {   // U3(0,0) for init fold, normal rows
            float2 M[4];
            u3m(u3p, M);
            d_fg4[160] = make_float4(M[0].x, M[0].y, M[1].x, M[1].y);
            d_fg4[161] = make_float4(M[2].x, M[2].y, M[3].x, M[3].y);
        }
        if (t < 40) {
            int b = t >> 3, w = t & 7;
            float2 U[4], C[4], B[4];
            if (w < 7)      u3m(u3p + (b * 8 + w + 1) * 3, U);
            else if (b < 4) u3m(u3p + ((b + 1) * 8) * 3, U);
            else { U[0] = make_float2(1, 0); U[1] = make_float2(0, 0);
                   U[2] = make_float2(0, 0); U[3] = make_float2(1, 0); }
            u3m(cu3p + (b * 8 + w) * 3, C);
            if (w < 7) mm2(C, U, B);   // U3 first, then CU3
            else       mm2(U, C, B);   // CU3(7,0) first, then next-block U3(.,0)
            float4* o = d_fg4 + t * 4;
            o[0] = make_float4(U[0].x, U[0].y, U[1].x, U[1].y);
            o[1] = make_float4(U[3].x, U[3].y, U[2].x, U[2].y);
            o[2] = make_float4(B[0].x, B[0].y, B[1].x, B[1].y);
            o[3] = make_float4(B[3].x, B[3].y, B[2].x, B[2].y);
        }
        return;
    }
    __shared__ float swt[8 * 144];
    __shared__ float sb[8];
    int tid = threadIdx.x;
    for (int i = tid; i < 8 * 144; i += 128) swt[i] = cw[i];
    if (tid < 8) sb[tid] = cb[tid];
    __syncthreads();

    // lane bits 0..2 = pixel-in-warp, lane bits 3..4 = ci-quarter
    int sub = (tid >> 3) & 3;
    int p   = blockIdx.x * 32 + (tid & 7) + ((tid >> 5) << 3);
    int bN = p >> 12, h = (p >> 6) & 63, wd = p & 63;

    float acc[8];
#pragma unroll
    for (int q = 0; q < 8; q++) acc[q] = 0.0f;

#pragma unroll
    for (int cc = 0; cc < 4; cc++) {
        int ci = sub * 4 + cc;
        const float* xp = x + ((bN * 16 + ci) << 12);
#pragma unroll
        for (int kh = 0; kh < 3; kh++) {
            int hh = h + kh - 1;
            if (hh < 0 || hh > 63) continue;
#pragma unroll
            for (int kw = 0; kw < 3; kw++) {
                int ww = wd + kw - 1;
                if (ww < 0 || ww > 63) continue;
                float xv = xp[hh * 64 + ww];
                int widx = ci * 9 + kh * 3 + kw;
#pragma unroll
                for (int q = 0; q < 8; q++) acc[q] += xv * swt[q * 144 + widx];
            }
        }
    }
    // reduce the 4 ci-quarters (lane bits 3 and 4)
#pragma unroll
    for (int q = 0; q < 8; q++) {
        acc[q] += __shfl_xor_sync(FULL, acc[q], 8);
        acc[q] += __shfl_xor_sync(FULL, acc[q], 16);
    }
    // each quarter writes 2 channels
    int q0 = sub * 2;
    d_ang[p * 8 + q0]     = acc[q0]     + sb[q0];
    d_ang[p * 8 + q0 + 1] = acc[q0 + 1] + sb[q0 + 1];
}

// ---------------------------------------------------------------------------
// Register-resident state: index i = lane + 32*k. Lane bits 0..4 = wires 7..3,
// k bits 0,1,2 = wires 2,1,0.
// ---------------------------------------------------------------------------
__device__ __forceinline__ void cpair(float& a0r, float& a0i, float& a1r, float& a1i,
                                      float2 u00, float2 u01, float2 u10, float2 u11) {
    float n0r = u00.x * a0r - u00.y * a0i + u01.x * a1r - u01.y * a1i;
    float n0i = u00.x * a0i + u00.y * a0r + u01.x * a1i + u01.y * a1r;
    float n1r = u10.x * a0r - u10.y * a0i + u11.x * a1r - u11.y * a1i;
    float n1i = u10.x * a0i + u10.y * a0r + u11.x * a1i + u11.y * a1r;
    a0r = n0r; a0i = n0i; a1r = n1r; a1i = n1i;
}

template <int Q>
__device__ __forceinline__ void lane_body(float* ar, float* ai, int k, float2 d0, float2 d1) {
    float orr = __shfl_xor_sync(FULL, ar[k], 1 << Q);
    float oii = __shfl_xor_sync(FULL, ai[k], 1 << Q);
    float nr = d0.x * ar[k] - d0.y * ai[k] + d1.x * orr - d1.y * oii;
    float ni = d0.x * ai[k] + d0.y * ar[k] + d1.x * oii + d1.y * orr;
    ar[k] = nr; ai[k] = ni;
}

// ---- fused CU3 gates (A = ctrl0, B = ctrl1, swizzled rows in g[0..3]) ----
template <int TB, int CB>
__device__ __forceinline__ void fgate_rr(float* ar, float* ai, const float4* g) {
    float4 a0 = g[0], a1 = g[1], b0 = g[2], b1 = g[3];
#pragma unroll
    for (int k0 = 0; k0 < 8; k0++)
        if (!(k0 & (1 << TB))) {
            float4 r0 = (k0 & (1 << CB)) ? b0 : a0;
            float4 r1 = (k0 & (1 << CB)) ? b1 : a1;
            int k1 = k0 | (1 << TB);
            cpair(ar[k0], ai[k0], ar[k1], ai[k1],
                  make_float2(r0.x, r0.y), make_float2(r0.z, r0.w),
                  make_float2(r1.z, r1.w), make_float2(r1.x, r1.y));
        }
}

__device__ __forceinline__ void fgate_lk(float* ar, float* ai, int lane, const float4* g) {
    int tb = (lane >> 4) & 1;
    float4 rA = g[tb];
    float4 rB = g[2 + tb];
    float2 d0A = make_float2(rA.x, rA.y), d1A = make_float2(rA.z, rA.w);
    float2 d0B = make_float2(rB.x, rB.y), d1B = make_float2(rB.z, rB.w);
#pragma unroll
    for (int k = 0; k < 8; k++)
        lane_body<4>(ar, ai, k, (k & 1) ? d0B : d0A, (k & 1) ? d1B : d1A);
}

template <int Q, int CQ>
__device__ __forceinline__ void fgate_ll(float* ar, float* ai, int lane, const float4* g) {
    int idx = (((lane >> CQ) & 1) << 1) | ((lane >> Q) & 1);
    float4 r = g[idx];
    float2 d0 = make_float2(r.x, r.y), d1 = make_float2(r.z, r.w);
#pragma unroll
    for (int k = 0; k < 8; k++) lane_body<Q>(ar, ai, k, d0, d1);
}

__device__ __forceinline__ void fgate_rl(float* ar, float* ai, int lane, const float4* g) {
    const float4* M = g + ((lane & 1) << 1);
    float4 r0 = M[0], r1 = M[1];
    float2 u00 = make_float2(r0.x, r0.y), u01 = make_float2(r0.z, r0.w);
    float2 u11 = make_float2(r1.x, r1.y), u10 = make_float2(r1.z, r1.w);
#pragma unroll
    for (int k0 = 0; k0 < 4; k0++)
        cpair(ar[k0], ai[k0], ar[k0 + 4], ai[k0 + 4], u00, u01, u10, u11);
}

// full-warp butterfly sum (all lanes get result)
__device__ __forceinline__ float wsum(float x) {
#pragma unroll
    for (int o = 16; o; o >>= 1) x += __shfl_xor_sync(FULL, x, o);
    return x;
}

// lane-wire <X>/<-Y> partials for lane bit Q: u = sum ar*or + ai*oi (gives <X>),
// v = sign * sum (ai*or - ar*oi) (gives my = -<Y>)
template <int Q>
__device__ __forceinline__ void xy_lane(const float* ar, const float* ai, int lane,
                                        float& uo, float& vo) {
    float uu = 0.0f, vv = 0.0f;
#pragma unroll
    for (int k = 0; k < 8; k++) {
        float orr = __shfl_xor_sync(FULL, ar[k], 1 << Q);
        float oii = __shfl_xor_sync(FULL, ai[k], 1 << Q);
        uu += ar[k] * orr + ai[k] * oii;
        vv += ai[k] * orr - ar[k] * oii;
    }
    uo = uu;
    vo = (lane & (1 << Q)) ? -vv : vv;
}

// ---------------------------------------------------------------------------
// Kernel 2: one warp per pixel. Main circuit + direct Pauli measurement.
// ---------------------------------------------------------------------------
__global__ void __launch_bounds__(128)
sim_kernel(const float* __restrict__ fc_w, const float* __restrict__ fc_b,
           float* __restrict__ out) {
    __shared__ float4 sg[162];
    int t = threadIdx.x, wp = t >> 5, lane = t & 31;
    int pix = blockIdx.x * 4 + wp;

    for (int i = t; i < 162; i += 128) sg[i] = d_fg4[i];

    float mys = 0.0f, myc = 1.0f;
    if (lane < 8) {
        float a = d_ang[pix * 8 + lane];
        sincosf(0.5f * a, &mys, &myc);
    }
    float cw[8], sw_[8];
#pragma unroll
    for (int w = 0; w < 8; w++) {
        cw[w]  = __shfl_sync(FULL, myc, w);
        sw_[w] = __shfl_sync(FULL, mys, w);
    }
    float lf = 1.0f;
#pragma unroll
    for (int q = 0; q < 5; q++) {          // lane bits 0..4 = wires 7..3
        int w = 7 - q;
        lf *= ((lane >> q) & 1) ? sw_[w] : cw[w];
    }
    __syncthreads();   // sg ready

    // fold U3(block0, wire0) into the wire-0 initial vector
    float4 M0 = sg[160], M1 = sg[161];
    float v0r = M0.x * cw[0] + M0.z * sw_[0];
    float v0i = M0.y * cw[0] + M0.w * sw_[0];
    float v1r = M1.x * cw[0] + M1.z * sw_[0];
    float v1i = M1.y * cw[0] + M1.w * sw_[0];

    float ar[8], ai[8];
#pragma unroll
    for (int k = 0; k < 8; k++) {
        float rp = lf * ((k & 1) ? sw_[2] : cw[2]) * ((k & 2) ? sw_[1] : cw[1]);
        ar[k] = rp * ((k & 4) ? v1r : v0r);
        ai[k] = rp * ((k & 4) ? v1i : v0i);
    }

    // 5 blocks of 8 fused CU3 gates (U3 layers absorbed)
#pragma unroll 1
    for (int b = 0; b < 5; b++) {
        const float4* gb = sg + b * 32;
        fgate_rr<1, 2>(ar, ai, gb + 0);         // c=w0(kb2), t=w1(kb1)
        fgate_rr<0, 1>(ar, ai, gb + 4);         // c=kb1, t=kb0
        fgate_lk(ar, ai, lane, gb + 8);         // c=kb0, t=lane4
        fgate_ll<3, 4>(ar, ai, lane, gb + 12);
        fgate_ll<2, 3>(ar, ai, lane, gb + 16);
        fgate_ll<1, 2>(ar, ai, lane, gb + 20);
        fgate_ll<0, 1>(ar, ai, lane, gb + 24);
        fgate_rl(ar, ai, lane, gb + 28);        // c=lane0, t=kb2
    }

    // ---- direct Pauli measurement (no basis-change layers) ----
    // mz: probabilities
    float p0 = ar[0]*ar[0] + ai[0]*ai[0], p1 = ar[1]*ar[1] + ai[1]*ai[1];
    float p2 = ar[2]*ar[2] + ai[2]*ai[2], p3 = ar[3]*ar[3] + ai[3]*ai[3];
    float p4 = ar[4]*ar[4] + ai[4]*ai[4], p5 = ar[5]*ar[5] + ai[5]*ai[5];
    float p6 = ar[6]*ar[6] + ai[6]*ai[6], p7 = ar[7]*ar[7] + ai[7]*ai[7];
    float sa = p0 + p1, sb2 = p2 + p3, sc = p4 + p5, sd = p6 + p7;
    float se = p0 + p2, sf = p4 + p6, sh = p1 + p3, si = p5 + p7;
    float tt = (sa + sb2) + (sc + sd);
    float z0 = (sa + sb2) - (sc + sd);      // wire0 (kb2)
    float z1 = (sa + sc) - (sb2 + sd);      // wire1 (kb1)
    float z2 = (se + sf) - (sh + si);       // wire2 (kb0)

    // Walsh-Hadamard of tt over lane bits: W(2^q) lands on lane 2^q
    float wt = tt;
#pragma unroll
    for (int o = 1; o <= 16; o <<= 1) {
        float r = __shfl_xor_sync(FULL, wt, o);
        wt = (lane & o) ? (r - wt) : (wt + r);
    }

    // reg-wire <X>/my partials (a0 = lower index); mx = 2*sum, my = 2*sum
    float u0 = 0, v0 = 0, u1 = 0, v1 = 0, u2 = 0, v2 = 0;
#pragma unroll
    for (int k = 0; k < 4; k++) {           // wire0: (k, k+4)
        u0 += ar[k] * ar[k+4] + ai[k] * ai[k+4];
        v0 += ai[k] * ar[k+4] - ar[k] * ai[k+4];
    }
#pragma unroll
    for (int k = 0; k < 8; k++)             // wire1: (k, k+2), bit1 clear
        if (!(k & 2)) {
            u1 += ar[k] * ar[k+2] + ai[k] * ai[k+2];
            v1 += ai[k] * ar[k+2] - ar[k] * ai[k+2];
        }
#pragma unroll
    for (int k = 0; k < 8; k += 2) {        // wire2: (k, k+1)
        u2 += ar[k] * ar[k+1] + ai[k] * ai[k+1];
        v2 += ai[k] * ar[k+1] - ar[k] * ai[k+1];
    }

    // lane-wire partials (wire 7-q for lane bit q)
    float ulq0, vlq0, ulq1, vlq1, ulq2, vlq2, ulq3, vlq3, ulq4, vlq4;
    xy_lane<0>(ar, ai, lane, ulq0, vlq0);   // wire7
    xy_lane<1>(ar, ai, lane, ulq1, vlq1);   // wire6
    xy_lane<2>(ar, ai, lane, ulq2, vlq2);   // wire5
    xy_lane<3>(ar, ai, lane, ulq3, vlq3);   // wire4
    xy_lane<4>(ar, ai, lane, ulq4, vlq4);   // wire3

    // reductions (results warp-uniform)
    float mz0 = wsum(z0), mz1 = wsum(z1), mz2 = wsum(z2);
    float mx0 = 2.0f * wsum(u0), mx1 = 2.0f * wsum(u1), mx2 = 2.0f * wsum(u2);
    float my0 = 2.0f * wsum(v0), my1 = 2.0f * wsum(v1), my2 = 2.0f * wsum(v2);
    float mx3 = wsum(ulq4), mx4 = wsum(ulq3), mx5 = wsum(ulq2);
    float mx6 = wsum(ulq1), mx7 = wsum(ulq0);
    float my3 = wsum(vlq4), my4 = wsum(vlq3), my5 = wsum(vlq2);
    float my6 = wsum(vlq1), my7 = wsum(vlq0);
    // mz for lane wires from Walsh lanes 16,8,4,2,1 (wires 3..7)
    float mz3 = __shfl_sync(FULL, wt, 16);
    float mz4 = __shfl_sync(FULL, wt, 8);
    float mz5 = __shfl_sync(FULL, wt, 4);
    float mz6 = __shfl_sync(FULL, wt, 2);
    float mz7 = __shfl_sync(FULL, wt, 1);

    // fused FC: one lane per output channel; fc_w row = 24 floats = 6 float4
    const float4* fw4 = (const float4*)fc_w + lane * 6;
    float4 w0 = __ldg(fw4 + 0), w1 = __ldg(fw4 + 1), w2 = __ldg(fw4 + 2);
    float4 w3 = __ldg(fw4 + 3), w4 = __ldg(fw4 + 4), w5 = __ldg(fw4 + 5);
    float o = __ldg(&fc_b[lane]);
    o += w0.x * mz0 + w0.y * mz1 + w0.z * mz2 + w0.w * mz3;
    o += w1.x * mz4 + w1.y * mz5 + w1.z * mz6 + w1.w * mz7;
    o += w2.x * mx0 + w2.y * mx1 + w2.z * mx2 + w2.w * mx3;
    o += w3.x * mx4 + w3.y * mx5 + w3.z * mx6 + w3.w * mx7;
    o += w4.x * my0 + w4.y * my1 + w4.z * my2 + w4.w * my3;
    o += w5.x * my4 + w5.y * my5 + w5.z * my6 + w5.w * my7;

    int bN = pix >> 12, hw = pix & 4095;
    out[(bN * 32 + lane) * 4096 + hw] = o;
}

// ---------------------------------------------------------------------------
extern "C" void kernel_launch(void* const* d_in, const int* in_sizes, int n_in,
                              void* d_out, int out_size) {
    const float* x      = (const float*)d_in[0];
    const float* conv_w = (const float*)d_in[1];
    const float* conv_b = (const float*)d_in[2];
    const float* u3p    = (const float*)d_in[3];
    const float* cu3p   = (const float*)d_in[4];
    const float* fc_w   = (const float*)d_in[5];
    const float* fc_b   = (const float*)d_in[6];
    float* out = (float*)d_out;

    conv_kernel<<<NPX / 32 + 1, 128>>>(x, conv_w, conv_b, u3p, cu3p);
    sim_kernel<<<NPX / 4, 128>>>(fc_w, fc_b, out);
}

// round 6
// speedup vs baseline: 6.4634x; 1.0046x over previous
#include <cuda_runtime.h>

typedef unsigned long long u64;
#define NPX 16384
#define FULL 0xffffffffu

// Scratch: conv angles, splatted gate coefficient rows, init U3.
// d_coef: 40 gates x 24 u64: [A row0(6), A row1(/sw)(6), B row0(6), B row1(/sw)(6)]
// row = [c0x, -c0y, c1x, -c1y, c0y, c1y] splatted; row1 swizzled (diag-first) for lane-target gates.
__device__ float  d_ang[NPX * 8];
__device__ u64    d_coef[960];
__device__ float4 d_initU[2];

// ---------------- packed f32x2 helpers ----------------
__device__ __forceinline__ u64 f2fma(u64 a, u64 b, u64 c) {
    u64 d; asm("fma.rn.f32x2 %0, %1, %2, %3;" : "=l"(d) : "l"(a), "l"(b), "l"(c)); return d;
}
__device__ __forceinline__ u64 f2mul(u64 a, u64 b) {
    u64 d; asm("mul.rn.f32x2 %0, %1, %2;" : "=l"(d) : "l"(a), "l"(b)); return d;
}
__device__ __forceinline__ u64 f2add(u64 a, u64 b) {
    u64 d; asm("add.rn.f32x2 %0, %1, %2;" : "=l"(d) : "l"(a), "l"(b)); return d;
}
__device__ __forceinline__ u64 pk(float a, float b) {
    u64 d; asm("mov.b64 %0, {%1, %2};" : "=l"(d) : "f"(a), "f"(b)); return d;
}
__device__ __forceinline__ void upk(u64 v, float& a, float& b) {
    asm("mov.b64 {%0, %1}, %2;" : "=f"(a), "=f"(b) : "l"(v));
}
__device__ __forceinline__ u64 dup(float v) {
    unsigned u = __float_as_uint(v); return ((u64)u << 32) | (u64)u;
}
__device__ __forceinline__ u64 shfl2(u64 v, int m) {
    float a, b; upk(v, a, b);
    a = __shfl_xor_sync(FULL, a, m);
    b = __shfl_xor_sync(FULL, b, m);
    return pk(a, b);
}
__device__ __forceinline__ u64 bshfl2(u64 v, int src) {
    float a, b; upk(v, a, b);
    a = __shfl_sync(FULL, a, src);
    b = __shfl_sync(FULL, b, src);
    return pk(a, b);
}
#define NEG1 dup(-1.0f)
#define POS1 dup(1.0f)
__device__ __forceinline__ u64 f2sub(u64 a, u64 b) { return f2fma(b, NEG1, a); }

// ---------------- setup helpers ----------------
__device__ __forceinline__ float2 cmul_(float2 a, float2 b) {
    return make_float2(a.x * b.x - a.y * b.y, a.x * b.y + a.y * b.x);
}
__device__ __forceinline__ float2 cadd_(float2 a, float2 b) {
    return make_float2(a.x + b.x, a.y + b.y);
}
__device__ void u3m(const float* p, float2* M) {
    float th = p[0], ph = p[1], la = p[2];
    float s, c;     sincosf(0.5f * th, &s, &c);
    float sl, cl;   sincosf(la, &sl, &cl);
    float sp, cp;   sincosf(ph, &sp, &cp);
    float spl, cpl; sincosf(ph + la, &spl, &cpl);
    M[0] = make_float2(c, 0.0f);
    M[1] = make_float2(-cl * s, -sl * s);
    M[2] = make_float2(cp * s, sp * s);
    M[3] = make_float2(cpl * c, spl * c);
}
__device__ void mm2(const float2* X, const float2* Y, float2* Z) {  // Z = X @ Y
    Z[0] = cadd_(cmul_(X[0], Y[0]), cmul_(X[1], Y[2]));
    Z[1] = cadd_(cmul_(X[0], Y[1]), cmul_(X[1], Y[3]));
    Z[2] = cadd_(cmul_(X[2], Y[0]), cmul_(X[3], Y[2]));
    Z[3] = cadd_(cmul_(X[2], Y[1]), cmul_(X[3], Y[3]));
}
// emit one matrix (12 u64 = row0 + row1/row1sw), all coefficients splatted
__device__ void emit_mat(u64* dst, const float2* M, bool sw) {
    dst[0] = dup(M[0].x); dst[1] = dup(-M[0].y); dst[2] = dup(M[1].x);
    dst[3] = dup(-M[1].y); dst[4] = dup(M[0].y); dst[5] = dup(M[1].y);
    float2 ma = sw ? M[3] : M[2];
    float2 mb = sw ? M[2] : M[3];
    dst[6] = dup(ma.x); dst[7] = dup(-ma.y); dst[8] = dup(mb.x);
    dst[9] = dup(-mb.y); dst[10] = dup(ma.y); dst[11] = dup(mb.y);
}

// ---------------------------------------------------------------------------
// Kernel 1: conv (4 threads/pixel, packed f32x2 over channel pairs)
// + last block: fused gate matrix setup.
// ---------------------------------------------------------------------------
__global__ void __launch_bounds__(128)
conv_kernel(const float* __restrict__ x, const float* __restrict__ cw,
            const float* __restrict__ cb, const float* __restrict__ u3p,
            const float* __restrict__ cu3p) {
    if (blockIdx.x == gridDim.x - 1) {
        int t = threadIdx.x;
        if (t == 40) {
            float2 M[4]; u3m(u3p, M);
            d_initU[0] = make_float4(M[0].x, M[0].y, M[1].x, M[1].y);
            d_initU[1] = make_float4(M[2].x, M[2].y, M[3].x, M[3].y);
        }
        if (t < 40) {
            int b = t >> 3, w = t & 7;
            float2 U[4], C[4], B[4];
            if (w < 7)      u3m(u3p + (b * 8 + w + 1) * 3, U);
            else if (b < 4) u3m(u3p + ((b + 1) * 8) * 3, U);
            else { U[0] = make_float2(1, 0); U[1] = make_float2(0, 0);
                   U[2] = make_float2(0, 0); U[3] = make_float2(1, 0); }
            u3m(cu3p + (b * 8 + w) * 3, C);
            if (w < 7) mm2(C, U, B);
            else       mm2(U, C, B);
            bool sw = (w >= 2 && w <= 6);   // lane-target gates use swizzled row1
            emit_mat(d_coef + t * 24,      U, sw);
            emit_mat(d_coef + t * 24 + 12, B, sw);
        }
        return;
    }
    __shared__ __align__(16) float wq[1152];   // wq[widx*8 + q] (transposed, u64-pair friendly)
    int tid = threadIdx.x;
    for (int i = tid; i < 1152; i += 128) {
        int q = i / 144, widx = i % 144;
        wq[widx * 8 + q] = cw[i];
    }
    __syncthreads();

    int sub = (tid >> 3) & 3;                       // ci-quarter (lane bits 3..4)
    int p   = blockIdx.x * 32 + (tid & 7) + ((tid >> 5) << 3);
    int bN = p >> 12, h = (p >> 6) & 63, wd = p & 63;

    u64 ACC[4] = {0, 0, 0, 0};
#pragma unroll
    for (int cc = 0; cc < 4; cc++) {
        int ci = sub * 4 + cc;
        const float* xp = x + ((bN * 16 + ci) << 12);
#pragma unroll
        for (int kh = 0; kh < 3; kh++) {
            int hh = h + kh - 1;
            if (hh < 0 || hh > 63) continue;
#pragma unroll
            for (int kw = 0; kw < 3; kw++) {
                int ww = wd + kw - 1;
                if (ww < 0 || ww > 63) continue;
                u64 xv2 = dup(xp[hh * 64 + ww]);
                const u64* wp_ = (const u64*)(wq + (ci * 9 + kh * 3 + kw) * 8);
                ACC[0] = f2fma(xv2, wp_[0], ACC[0]);
                ACC[1] = f2fma(xv2, wp_[1], ACC[1]);
                ACC[2] = f2fma(xv2, wp_[2], ACC[2]);
                ACC[3] = f2fma(xv2, wp_[3], ACC[3]);
            }
        }
    }
#pragma unroll
    for (int j = 0; j < 4; j++) {
        ACC[j] = f2add(ACC[j], shfl2(ACC[j], 8));
        ACC[j] = f2add(ACC[j], shfl2(ACC[j], 16));
    }
    float lo, hi; upk(ACC[sub], lo, hi);
    int q0 = sub * 2;
    *(float2*)&d_ang[p * 8 + q0] = make_float2(lo + cb[q0], hi + cb[q0 + 1]);
}

// ---------------------------------------------------------------------------
// Gate primitives: u64 halves = (pixelA, pixelB). k bits 0,1,2 = wires 2,1,0;
// lane bits 0..4 = wires 7..3.
// ---------------------------------------------------------------------------
__device__ __forceinline__ void cpair2(u64& a0r, u64& a0i, u64& a1r, u64& a1i,
                                       const u64* r) {
    u64 n0r = f2fma(r[0], a0r, f2fma(r[1], a0i, f2fma(r[2],  a1r, f2mul(r[3],  a1i))));
    u64 n0i = f2fma(r[4], a0r, f2fma(r[0], a0i, f2fma(r[5],  a1r, f2mul(r[2],  a1i))));
    u64 n1r = f2fma(r[6], a0r, f2fma(r[7], a0i, f2fma(r[8],  a1r, f2mul(r[9],  a1i))));
    u64 n1i = f2fma(r[10],a0r, f2fma(r[6], a0i, f2fma(r[11], a1r, f2mul(r[8],  a1i))));
    a0r = n0r; a0i = n0i; a1r = n1r; a1i = n1i;
}

template <int TB, int CB>
__device__ __forceinline__ void g_rr(u64* AR, u64* AI, const u64* g) {
#pragma unroll
    for (int k0 = 0; k0 < 8; k0++)
        if (!(k0 & (1 << TB))) {
            const u64* r = g + ((k0 & (1 << CB)) ? 12 : 0);
            int k1 = k0 | (1 << TB);
            cpair2(AR[k0], AI[k0], AR[k1], AI[k1], r);
        }
}

__device__ __forceinline__ void g_rl(u64* AR, u64* AI, int lane, const u64* g) {
    const u64* r = g + ((lane & 1) ? 12 : 0);
#pragma unroll
    for (int k0 = 0; k0 < 4; k0++)
        cpair2(AR[k0], AI[k0], AR[k0 + 4], AI[k0 + 4], r);
}

__device__ __forceinline__ void lrow(u64& ar, u64& ai, int msk,
                                     u64 c0, u64 c1, u64 c2, u64 c3, u64 c4, u64 c5) {
    u64 xr = shfl2(ar, msk), xi = shfl2(ai, msk);
    u64 nr = f2fma(c0, ar, f2fma(c1, ai, f2fma(c2, xr, f2mul(c3, xi))));
    u64 ni = f2fma(c4, ar, f2fma(c0, ai, f2fma(c5, xr, f2mul(c2, xi))));
    ar = nr; ai = ni;
}

template <int Q, int CQ>
__device__ __forceinline__ void g_ll(u64* AR, u64* AI, int lane, const u64* g) {
    const u64* r = g + ((((lane >> CQ) & 1) << 1) | ((lane >> Q) & 1)) * 6;
    u64 c0 = r[0], c1 = r[1], c2 = r[2], c3 = r[3], c4 = r[4], c5 = r[5];
#pragma unroll
    for (int k = 0; k < 8; k++) lrow(AR[k], AI[k], 1 << Q, c0, c1, c2, c3, c4, c5);
}

__device__ __forceinline__ void g_lk(u64* AR, u64* AI, int lane, const u64* g) {
    int tb = (lane >> 4) & 1;
    const u64* rA = g + tb * 6;
    const u64* rB = g + 12 + tb * 6;
    u64 a0 = rA[0], a1 = rA[1], a2 = rA[2], a3 = rA[3], a4 = rA[4], a5 = rA[5];
    u64 b0 = rB[0], b1 = rB[1], b2 = rB[2], b3 = rB[3], b4 = rB[4], b5 = rB[5];
#pragma unroll
    for (int k = 0; k < 8; k++) {
        if (k & 1) lrow(AR[k], AI[k], 16, b0, b1, b2, b3, b4, b5);
        else       lrow(AR[k], AI[k], 16, a0, a1, a2, a3, a4, a5);
    }
}

__device__ __forceinline__ u64 wsum2(u64 x) {
#pragma unroll
    for (int o = 16; o; o >>= 1) x = f2add(x, shfl2(x, o));
    return x;
}

template <int MSK>
__device__ __forceinline__ void xy2(const u64* AR, const u64* AI, int lane,
                                    u64& uo, u64& vo) {
    u64 uu = 0, vp = 0, vm = 0;
#pragma unroll
    for (int k = 0; k < 8; k++) {
        u64 xr = shfl2(AR[k], MSK), xi = shfl2(AI[k], MSK);
        uu = f2fma(AR[k], xr, f2fma(AI[k], xi, uu));
        vp = f2fma(AI[k], xr, vp);
        vm = f2fma(AR[k], xi, vm);
    }
    uo = uu;
    u64 vv = f2sub(vp, vm);
    vo = (lane & MSK) ? f2mul(vv, NEG1) : vv;
}

// ---------------------------------------------------------------------------
// Kernel 2: one warp per TWO pixels (f32x2-packed statevector).
// ---------------------------------------------------------------------------
__global__ void __launch_bounds__(128)
sim_kernel(const float* __restrict__ fc_w, const float* __restrict__ fc_b,
           float* __restrict__ out) {
    __shared__ u64 sco[960];
    __shared__ float4 sinit[2];
    int t = threadIdx.x, wp = t >> 5, lane = t & 31;
    int pbase = blockIdx.x * 8 + wp * 2;           // even pixel; warp covers pbase, pbase+1

    for (int i = t; i < 960; i += 128) sco[i] = d_coef[i];
    if (t < 2) sinit[t] = d_initU[t];

    // angles: lanes 0..7 pixel A, 8..15 pixel B
    float mys = 0.0f, myc = 1.0f;
    if (lane < 16) {
        float a = d_ang[pbase * 8 + lane];
        sincosf(0.5f * a, &mys, &myc);
    }
    u64 cwp[8], swp[8];
#pragma unroll
    for (int w = 0; w < 8; w++) {
        cwp[w] = pk(__shfl_sync(FULL, myc, w), __shfl_sync(FULL, myc, w + 8));
        swp[w] = pk(__shfl_sync(FULL, mys, w), __shfl_sync(FULL, mys, w + 8));
    }
    u64 LF = POS1;
#pragma unroll
    for (int q = 0; q < 5; q++)                     // lane bits 0..4 = wires 7..3
        LF = f2mul(LF, ((lane >> q) & 1) ? swp[7 - q] : cwp[7 - q]);
    __syncthreads();   // sco + sinit ready

    // fold U3(block0, wire0) into the wire-0 initial vector
    float4 M0 = sinit[0], M1 = sinit[1];
    u64 V0R = f2fma(dup(M0.x), cwp[0], f2mul(dup(M0.z), swp[0]));
    u64 V0I = f2fma(dup(M0.y), cwp[0], f2mul(dup(M0.w), swp[0]));
    u64 V1R = f2fma(dup(M1.x), cwp[0], f2mul(dup(M1.z), swp[0]));
    u64 V1I = f2fma(dup(M1.y), cwp[0], f2mul(dup(M1.w), swp[0]));

    u64 AR[8], AI[8];
#pragma unroll
    for (int k = 0; k < 8; k++) {
        u64 RP = f2mul(f2mul(LF, (k & 1) ? swp[2] : cwp[2]), (k & 2) ? swp[1] : cwp[1]);
        AR[k] = f2mul(RP, (k & 4) ? V1R : V0R);
        AI[k] = f2mul(RP, (k & 4) ? V1I : V0I);
    }

    // 5 blocks of 8 fused CU3 gates
#pragma unroll 1
    for (int b = 0; b < 5; b++) {
        const u64* gb = sco + b * 192;
        g_rr<1, 2>(AR, AI, gb + 0);        // c=w0(kb2), t=w1(kb1)
        g_rr<0, 1>(AR, AI, gb + 24);       // c=kb1, t=kb0
        g_lk(AR, AI, lane, gb + 48);       // c=kb0, t=lane4
        g_ll<3, 4>(AR, AI, lane, gb + 72);
        g_ll<2, 3>(AR, AI, lane, gb + 96);
        g_ll<1, 2>(AR, AI, lane, gb + 120);
        g_ll<0, 1>(AR, AI, lane, gb + 144);
        g_rl(AR, AI, lane, gb + 168);      // c=lane0, t=kb2
    }

    // ---- packed direct Pauli measurement ----
    u64 PP[8];
#pragma unroll
    for (int k = 0; k < 8; k++) PP[k] = f2fma(AR[k], AR[k], f2mul(AI[k], AI[k]));
    u64 sa = f2add(PP[0], PP[1]), sb = f2add(PP[2], PP[3]);
    u64 sc = f2add(PP[4], PP[5]), sd = f2add(PP[6], PP[7]);
    u64 se = f2add(PP[0], PP[2]), sf = f2add(PP[4], PP[6]);
    u64 sh = f2add(PP[1], PP[3]), si = f2add(PP[5], PP[7]);
    u64 ab = f2add(sa, sb), cd = f2add(sc, sd);
    u64 tt = f2add(ab, cd);
    u64 z0 = f2sub(ab, cd);
    u64 z1 = f2sub(f2add(sa, sc), f2add(sb, sd));
    u64 z2 = f2sub(f2add(se, sf), f2add(sh, si));

    // Walsh-Hadamard of tt over lane bits (packed): W(2^q) lands on lane 2^q
    u64 wt = tt;
#pragma unroll
    for (int o = 1; o <= 16; o <<= 1) {
        u64 r = shfl2(wt, o);
        wt = f2fma(wt, (lane & o) ? NEG1 : POS1, r);
    }

    // reg-wire <X>/my partials
    u64 u0 = 0, v0p = 0, v0m = 0, u1 = 0, v1p = 0, v1m = 0, u2 = 0, v2p = 0, v2m = 0;
#pragma unroll
    for (int k = 0; k < 4; k++) {                 // wire0: (k, k+4)
        u0  = f2fma(AR[k], AR[k + 4], f2fma(AI[k], AI[k + 4], u0));
        v0p = f2fma(AI[k], AR[k + 4], v0p);
        v0m = f2fma(AR[k], AI[k + 4], v0m);
    }
#pragma unroll
    for (int k = 0; k < 8; k++)                   // wire1: (k, k+2)
        if (!(k & 2)) {
            u1  = f2fma(AR[k], AR[k + 2], f2fma(AI[k], AI[k + 2], u1));
            v1p = f2fma(AI[k], AR[k + 2], v1p);
            v1m = f2fma(AR[k], AI[k + 2], v1m);
        }
#pragma unroll
    for (int k = 0; k < 8; k += 2) {              // wire2: (k, k+1)
        u2  = f2fma(AR[k], AR[k + 1], f2fma(AI[k], AI[k + 1], u2));
        v2p = f2fma(AI[k], AR[k + 1], v2p);
        v2m = f2fma(AR[k], AI[k + 1], v2m);
    }
    u64 v0 = f2sub(v0p, v0m), v1 = f2sub(v1p, v1m), v2 = f2sub(v2p, v2m);

    // lane-wire partials
    u64 ul0, vl0, ul1, vl1, ul2, vl2, ul3, vl3, ul4, vl4;
    xy2<1>(AR, AI, lane, ul0, vl0);               // wire7
    xy2<2>(AR, AI, lane, ul1, vl1);               // wire6
    xy2<4>(AR, AI, lane, ul2, vl2);               // wire5
    xy2<8>(AR, AI, lane, ul3, vl3);               // wire4
    xy2<16>(AR, AI, lane, ul4, vl4);              // wire3

    u64 TWO = dup(2.0f);
    u64 mz0 = wsum2(z0), mz1 = wsum2(z1), mz2 = wsum2(z2);
    u64 mx0 = f2mul(TWO, wsum2(u0)), mx1 = f2mul(TWO, wsum2(u1)), mx2 = f2mul(TWO, wsum2(u2));
    u64 my0 = f2mul(TWO, wsum2(v0)), my1 = f2mul(TWO, wsum2(v1)), my2 = f2mul(TWO, wsum2(v2));
    u64 mx3 = wsum2(ul4), mx4 = wsum2(ul3), mx5 = wsum2(ul2);
    u64 mx6 = wsum2(ul1), mx7 = wsum2(ul0);
    u64 my3 = wsum2(vl4), my4 = wsum2(vl3), my5 = wsum2(vl2);
    u64 my6 = wsum2(vl1), my7 = wsum2(vl0);
    u64 mz3 = bshfl2(wt, 16), mz4 = bshfl2(wt, 8), mz5 = bshfl2(wt, 4);
    u64 mz6 = bshfl2(wt, 2),  mz7 = bshfl2(wt, 1);

    // fused FC (packed: both pixels at once); one lane per output channel
    const float4* fw4 = (const float4*)fc_w + lane * 6;
    float4 w0 = __ldg(fw4 + 0), w1 = __ldg(fw4 + 1), w2 = __ldg(fw4 + 2);
    float4 w3 = __ldg(fw4 + 3), w4 = __ldg(fw4 + 4), w5 = __ldg(fw4 + 5);
    float bia = __ldg(&fc_b[lane]);
    u64 o = pk(bia, bia);
    o = f2fma(mz0, pk(w0.x, w0.x), o); o = f2fma(mz1, pk(w0.y, w0.y), o);
    o = f2fma(mz2, pk(w0.z, w0.z), o); o = f2fma(mz3, pk(w0.w, w0.w), o);
    o = f2fma(mz4, pk(w1.x, w1.x), o); o = f2fma(mz5, pk(w1.y, w1.y), o);
    o = f2fma(mz6, pk(w1.z, w1.z), o); o = f2fma(mz7, pk(w1.w, w1.w), o);
    o = f2fma(mx0, pk(w2.x, w2.x), o); o = f2fma(mx1, pk(w2.y, w2.y), o);
    o = f2fma(mx2, pk(w2.z, w2.z), o); o = f2fma(mx3, pk(w2.w, w2.w), o);
    o = f2fma(mx4, pk(w3.x, w3.x), o); o = f2fma(mx5, pk(w3.y, w3.y), o);
    o = f2fma(mx6, pk(w3.z, w3.z), o); o = f2fma(mx7, pk(w3.w, w3.w), o);
    o = f2fma(my0, pk(w4.x, w4.x), o); o = f2fma(my1, pk(w4.y, w4.y), o);
    o = f2fma(my2, pk(w4.z, w4.z), o); o = f2fma(my3, pk(w4.w, w4.w), o);
    o = f2fma(my4, pk(w5.x, w5.x), o); o = f2fma(my5, pk(w5.y, w5.y), o);
    o = f2fma(my6, pk(w5.z, w5.z), o); o = f2fma(my7, pk(w5.w, w5.w), o);

    float oA, oB; upk(o, oA, oB);
    int bN = pbase >> 12, hw = pbase & 4095;       // pbase even -> same image row region
    *(float2*)&out[(bN * 32 + lane) * 4096 + hw] = make_float2(oA, oB);
}

// ---------------------------------------------------------------------------
extern "C" void kernel_launch(void* const* d_in, const int* in_sizes, int n_in,
                              void* d_out, int out_size) {
    const float* x      = (const float*)d_in[0];
    const float* conv_w = (const float*)d_in[1];
    const float* conv_b = (const float*)d_in[2];
    const float* u3p    = (const float*)d_in[3];
    const float* cu3p   = (const float*)d_in[4];
    const float* fc_w   = (const float*)d_in[5];
    const float* fc_b   = (const float*)d_in[6];
    float* out = (float*)d_out;

    conv_kernel<<<NPX / 32 + 1, 128>>>(x, conv_w, conv_b, u3p, cu3p);
    sim_kernel<<<NPX / 8, 128>>>(fc_w, fc_b, out);
}